// round 6
// baseline (speedup 1.0000x reference)
#include <cuda_runtime.h>

#define N 128
#define N2 (N*N)
#define N3 (N*N*N)

static constexpr int S64 = 64*64*64;
static constexpr int S32 = 32*32*32;

static constexpr size_t O_U   = 0;
static constexpr size_t O_V   = (size_t)1*N3;
static constexpr size_t O_W   = (size_t)2*N3;
static constexpr size_t O_BU  = (size_t)3*N3;
static constexpr size_t O_BV  = (size_t)4*N3;
static constexpr size_t O_BW  = (size_t)5*N3;
static constexpr size_t O_B   = (size_t)6*N3;
static constexpr size_t O_R0  = (size_t)7*N3;
static constexpr size_t O_F   = (size_t)8*N3;
static constexpr size_t O_R1  = (size_t)9*N3;
static constexpr size_t O_R2  = O_R1 + S64;
static constexpr size_t O_W32 = O_R2 + S32;
static constexpr size_t O_W64 = O_W32 + S32;
static constexpr size_t SCRATCH_TOT = O_W64 + S64;

__device__ float g_scratch[SCRATCH_TOT];

// ---------------- vector helpers ----------------

__device__ __forceinline__ float4 ld4(const float* __restrict__ p) {
    return *(const float4*)p;
}
__device__ __forceinline__ void st4(float* __restrict__ p, float4 v) {
    *(float4*)p = v;
}

struct VSt {             // 7-point stencil data for 4 consecutive x cells
    float4 c;
    float  w, e;
    float4 s, n, b, t;
};

// z-pair stencil data: everything needed for outputs at z=k and z=k+1
struct ZPair {
    float4 c0, c1;        // centers at k, k+1
    float  w0, e0, w1, e1;
    float4 s0, n0, s1, n1;
    float4 bm, tp;        // planes k-1 and k+2 (clamped)
};

__device__ __forceinline__ ZPair ldz(const float* __restrict__ A, int id,
                                     int i4, int j, int k, bool bcu) {
    ZPair z;
    int id1 = id + N2;
    z.c0 = ld4(A + id);
    z.c1 = ld4(A + id1);
    z.w0 = (i4 > 0)     ? A[id - 1]   : (bcu ? 1.0f : z.c0.x);
    z.e0 = (i4 < N - 4) ? A[id + 4]   : z.c0.w;
    z.w1 = (i4 > 0)     ? A[id1 - 1]  : (bcu ? 1.0f : z.c1.x);
    z.e1 = (i4 < N - 4) ? A[id1 + 4]  : z.c1.w;
    z.s0 = (j > 0)      ? ld4(A + id - N)   : z.c0;
    z.n0 = (j < N - 1)  ? ld4(A + id + N)   : z.c0;
    z.s1 = (j > 0)      ? ld4(A + id1 - N)  : z.c1;
    z.n1 = (j < N - 1)  ? ld4(A + id1 + N)  : z.c1;
    z.bm = (k > 0)      ? ld4(A + id - N2)  : z.c0;
    z.tp = (k + 2 < N)  ? ld4(A + id1 + N2) : z.c1;
    return z;
}

__device__ __forceinline__ VSt vz0(const ZPair& z) {
    VSt r; r.c = z.c0; r.w = z.w0; r.e = z.e0;
    r.s = z.s0; r.n = z.n0; r.b = z.bm; r.t = z.c1; return r;
}
__device__ __forceinline__ VSt vz1(const ZPair& z) {
    VSt r; r.c = z.c1; r.w = z.w1; r.e = z.e1;
    r.s = z.s1; r.n = z.n1; r.b = z.c0; r.t = z.tp; return r;
}

__device__ __forceinline__ float4 westv(const VSt& s) {
    return make_float4(s.w, s.c.x, s.c.y, s.c.z);
}
__device__ __forceinline__ float4 eastv(const VSt& s) {
    return make_float4(s.c.y, s.c.z, s.c.w, s.e);
}
__device__ __forceinline__ float4 gradx(const VSt& s) {
    float4 w = westv(s), e = eastv(s);
    return make_float4(0.5f*(e.x-w.x), 0.5f*(e.y-w.y), 0.5f*(e.z-w.z), 0.5f*(e.w-w.w));
}
__device__ __forceinline__ float4 grady(const VSt& s) {
    return make_float4(0.5f*(s.n.x-s.s.x), 0.5f*(s.n.y-s.s.y),
                       0.5f*(s.n.z-s.s.z), 0.5f*(s.n.w-s.s.w));
}
__device__ __forceinline__ float4 gradz(const VSt& s) {
    return make_float4(0.5f*(s.t.x-s.b.x), 0.5f*(s.t.y-s.b.y),
                       0.5f*(s.t.z-s.b.z), 0.5f*(s.t.w-s.b.w));
}
__device__ __forceinline__ float4 lap4(const VSt& s) {
    float4 w = westv(s), e = eastv(s);
    return make_float4(w.x+e.x+s.s.x+s.n.x+s.b.x+s.t.x-6.f*s.c.x,
                       w.y+e.y+s.s.y+s.n.y+s.b.y+s.t.y-6.f*s.c.y,
                       w.z+e.z+s.s.z+s.n.z+s.b.z+s.t.z-6.f*s.c.z,
                       w.w+e.w+s.s.w+s.n.w+s.b.w+s.t.w-6.f*s.c.w);
}

// (base + cdt*(lap(S) - A1*dSx - A2*dSy - A3*dSz) - dt*grad) * f
__device__ __forceinline__ float4 mom_rhs(const VSt& S, float4 base,
                                          float4 A1, float4 A2, float4 A3,
                                          float4 grad, float4 f,
                                          float cdt, float dt)
{
    float4 wv = westv(S), ev = eastv(S);
    float4 out;
    const float* pw = &wv.x;   const float* pe = &ev.x;
    const float* ps = &S.s.x;  const float* pn = &S.n.x;
    const float* pb = &S.b.x;  const float* pt = &S.t.x;
    const float* pc = &S.c.x;  const float* pba = &base.x;
    const float* p1 = &A1.x;   const float* p2 = &A2.x;  const float* p3 = &A3.x;
    const float* pg = &grad.x; const float* pf = &f.x;
    float* po = &out.x;
    #pragma unroll
    for (int m = 0; m < 4; ++m) {
        float lap = pw[m]+pe[m]+ps[m]+pn[m]+pb[m]+pt[m] - 6.f*pc[m];
        float ax = 0.5f*(pe[m]-pw[m]);
        float ay = 0.5f*(pn[m]-ps[m]);
        float az = 0.5f*(pt[m]-pb[m]);
        po[m] = (pba[m] + cdt*(lap - p1[m]*ax - p2[m]*ay - p3[m]*az) - dt*pg[m]) * pf[m];
    }
    return out;
}

// ---------------- kernels ----------------

__global__ void k_solid(const float4* __restrict__ vu, const float4* __restrict__ vv,
                        const float4* __restrict__ vw, const float4* __restrict__ sg,
                        const float* __restrict__ dtp,
                        float4* __restrict__ u, float4* __restrict__ v,
                        float4* __restrict__ w, float4* __restrict__ F)
{
    int id = blockIdx.x * blockDim.x + threadIdx.x;
    float dt = dtp[0];
    float4 s = sg[id];
    float4 f;
    f.x = __fdividef(1.0f, 1.0f + dt * s.x);
    f.y = __fdividef(1.0f, 1.0f + dt * s.y);
    f.z = __fdividef(1.0f, 1.0f + dt * s.z);
    f.w = __fdividef(1.0f, 1.0f + dt * s.w);
    float4 a = vu[id]; a.x *= f.x; a.y *= f.y; a.z *= f.z; a.w *= f.w; u[id] = a;
    float4 b = vv[id]; b.x *= f.x; b.y *= f.y; b.z *= f.z; b.w *= f.w; v[id] = b;
    float4 c = vw[id]; c.x *= f.x; c.y *= f.y; c.z *= f.z; c.w *= f.w; w[id] = c;
    F[id] = f;
}

__global__ void __launch_bounds__(256)
k_predictor(const float* __restrict__ u, const float* __restrict__ v,
            const float* __restrict__ w, const float* __restrict__ p,
            const float* __restrict__ F, const float* __restrict__ dtp,
            float* __restrict__ bu, float* __restrict__ bv,
            float* __restrict__ bw)
{
    int i4 = threadIdx.x * 4;
    int j = blockIdx.y * blockDim.y + threadIdx.y;
    int tz = blockIdx.z * blockDim.z + threadIdx.z;
    int k = tz * 2;
    int id = (k * N + j) * N + i4;
    int id1 = id + N2;
    float dt = dtp[0], hdt = 0.5f * dt;

    float4 f0 = ld4(F + id),  f1 = ld4(F + id1);
    float4 uc0 = ld4(u + id), uc1 = ld4(u + id1);
    float4 vc0 = ld4(v + id), vc1 = ld4(v + id1);
    float4 wc0 = ld4(w + id), wc1 = ld4(w + id1);

    ZPair P = ldz(p, id, i4, j, k, false);
    VSt P0 = vz0(P), P1 = vz1(P);
    float4 px0 = gradx(P0), py0 = grady(P0), pz0 = gradz(P0);
    float4 px1 = gradx(P1), py1 = grady(P1), pz1 = gradz(P1);

    {
        ZPair S = ldz(u, id, i4, j, k, true);
        st4(bu + id,  mom_rhs(vz0(S), uc0, uc0, vc0, wc0, px0, f0, hdt, dt));
        st4(bu + id1, mom_rhs(vz1(S), uc1, uc1, vc1, wc1, px1, f1, hdt, dt));
    }
    {
        ZPair S = ldz(v, id, i4, j, k, false);
        st4(bv + id,  mom_rhs(vz0(S), vc0, uc0, vc0, wc0, py0, f0, hdt, dt));
        st4(bv + id1, mom_rhs(vz1(S), vc1, uc1, vc1, wc1, py1, f1, hdt, dt));
    }
    {
        ZPair S = ldz(w, id, i4, j, k, false);
        st4(bw + id,  mom_rhs(vz0(S), wc0, uc0, vc0, wc0, pz0, f0, hdt, dt));
        st4(bw + id1, mom_rhs(vz1(S), wc1, uc1, vc1, wc1, pz1, f1, hdt, dt));
    }
}

__global__ void __launch_bounds__(256)
k_corrector(const float* __restrict__ bu, const float* __restrict__ bv,
            const float* __restrict__ bw, const float* __restrict__ p,
            const float* __restrict__ F, const float* __restrict__ dtp,
            float* __restrict__ u, float* __restrict__ v,
            float* __restrict__ w)
{
    int i4 = threadIdx.x * 4;
    int j = blockIdx.y * blockDim.y + threadIdx.y;
    int tz = blockIdx.z * blockDim.z + threadIdx.z;
    int k = tz * 2;
    int id = (k * N + j) * N + i4;
    int id1 = id + N2;
    float dt = dtp[0];

    float4 f0 = ld4(F + id),  f1 = ld4(F + id1);
    float4 uc0 = ld4(u + id), uc1 = ld4(u + id1);
    float4 vc0 = ld4(v + id), vc1 = ld4(v + id1);
    float4 wc0 = ld4(w + id), wc1 = ld4(w + id1);
    float4 bu0 = ld4(bu + id), bu1 = ld4(bu + id1);
    float4 bv0 = ld4(bv + id), bv1 = ld4(bv + id1);
    float4 bw0 = ld4(bw + id), bw1 = ld4(bw + id1);

    ZPair P = ldz(p, id, i4, j, k, false);
    VSt P0 = vz0(P), P1 = vz1(P);
    float4 px0 = gradx(P0), py0 = grady(P0), pz0 = gradz(P0);
    float4 px1 = gradx(P1), py1 = grady(P1), pz1 = gradz(P1);

    float4 un0, un1, vn0, vn1, wn0, wn1;
    {
        ZPair S = ldz(bu, id, i4, j, k, true);
        un0 = mom_rhs(vz0(S), uc0, bu0, bv0, bw0, px0, f0, dt, dt);
        un1 = mom_rhs(vz1(S), uc1, bu1, bv1, bw1, px1, f1, dt, dt);
    }
    {
        ZPair S = ldz(bv, id, i4, j, k, false);
        vn0 = mom_rhs(vz0(S), vc0, bu0, bv0, bw0, py0, f0, dt, dt);
        vn1 = mom_rhs(vz1(S), vc1, bu1, bv1, bw1, py1, f1, dt, dt);
    }
    {
        ZPair S = ldz(bw, id, i4, j, k, false);
        wn0 = mom_rhs(vz0(S), wc0, bu0, bv0, bw0, pz0, f0, dt, dt);
        wn1 = mom_rhs(vz1(S), wc1, bu1, bv1, bw1, pz1, f1, dt, dt);
    }
    st4(u + id, un0);  st4(u + id1, un1);
    st4(v + id, vn0);  st4(v + id1, vn1);
    st4(w + id, wn0);  st4(w + id1, wn1);
}

// fused: b = -div(u,v,w)/dt  AND  r0 = lap(p) - b, two z-planes per thread
__global__ void __launch_bounds__(256)
k_divres(const float* __restrict__ u, const float* __restrict__ v,
         const float* __restrict__ w, const float* __restrict__ p,
         const float* __restrict__ dtp,
         float* __restrict__ bArr, float* __restrict__ r0)
{
    int i4 = threadIdx.x * 4;
    int j = blockIdx.y * blockDim.y + threadIdx.y;
    int tz = blockIdx.z * blockDim.z + threadIdx.z;
    int k = tz * 2;
    int id = (k * N + j) * N + i4;
    int id1 = id + N2;
    float nh = -0.5f * __fdividef(1.0f, dtp[0]);

    // u: x-gradient at both z
    float4 uc0 = ld4(u + id), uc1 = ld4(u + id1);
    float uw0 = (i4 > 0)     ? u[id - 1]  : 1.0f;
    float ue0 = (i4 < N - 4) ? u[id + 4]  : uc0.w;
    float uw1 = (i4 > 0)     ? u[id1 - 1] : 1.0f;
    float ue1 = (i4 < N - 4) ? u[id1 + 4] : uc1.w;

    // v: y-gradient at both z
    float4 vc0 = ld4(v + id), vc1 = ld4(v + id1);
    float4 vs0 = (j > 0)     ? ld4(v + id - N)  : vc0;
    float4 vn0 = (j < N - 1) ? ld4(v + id + N)  : vc0;
    float4 vs1 = (j > 0)     ? ld4(v + id1 - N) : vc1;
    float4 vn1 = (j < N - 1) ? ld4(v + id1 + N) : vc1;

    // w: z-gradient at both z (planes k-1..k+2)
    float4 wc0 = ld4(w + id), wc1 = ld4(w + id1);
    float4 wb = (k > 0)     ? ld4(w + id - N2)  : wc0;
    float4 wt = (k + 2 < N) ? ld4(w + id1 + N2) : wc1;

    ZPair P = ldz(p, id, i4, j, k, false);

    {   // z = k
        float4 wv = make_float4(uw0, uc0.x, uc0.y, uc0.z);
        float4 ev = make_float4(uc0.y, uc0.z, uc0.w, ue0);
        float4 b;
        b.x = nh * ((ev.x - wv.x) + (vn0.x - vs0.x) + (wc1.x - wb.x));
        b.y = nh * ((ev.y - wv.y) + (vn0.y - vs0.y) + (wc1.y - wb.y));
        b.z = nh * ((ev.z - wv.z) + (vn0.z - vs0.z) + (wc1.z - wb.z));
        b.w = nh * ((ev.w - wv.w) + (vn0.w - vs0.w) + (wc1.w - wb.w));
        st4(bArr + id, b);
        float4 lp = lap4(vz0(P));
        st4(r0 + id, make_float4(lp.x - b.x, lp.y - b.y, lp.z - b.z, lp.w - b.w));
    }
    {   // z = k+1
        float4 wv = make_float4(uw1, uc1.x, uc1.y, uc1.z);
        float4 ev = make_float4(uc1.y, uc1.z, uc1.w, ue1);
        float4 b;
        b.x = nh * ((ev.x - wv.x) + (vn1.x - vs1.x) + (wt.x - wc0.x));
        b.y = nh * ((ev.y - wv.y) + (vn1.y - vs1.y) + (wt.y - wc0.y));
        b.z = nh * ((ev.z - wv.z) + (vn1.z - vs1.z) + (wt.z - wc0.z));
        b.w = nh * ((ev.w - wv.w) + (vn1.w - vs1.w) + (wt.w - wc0.w));
        st4(bArr + id1, b);
        float4 lp = lap4(vz1(P));
        st4(r0 + id1, make_float4(lp.x - b.x, lp.y - b.y, lp.z - b.z, lp.w - b.w));
    }
}

__global__ void __launch_bounds__(256)
k_residual(const float* __restrict__ p, const float* __restrict__ b,
           float* __restrict__ r0)
{
    int i4 = threadIdx.x * 4;
    int j = blockIdx.y * blockDim.y + threadIdx.y;
    int tz = blockIdx.z * blockDim.z + threadIdx.z;
    int k = tz * 2;
    int id = (k * N + j) * N + i4;
    int id1 = id + N2;

    ZPair P = ldz(p, id, i4, j, k, false);
    float4 b0 = ld4(b + id), b1 = ld4(b + id1);
    float4 l0 = lap4(vz0(P)), l1 = lap4(vz1(P));
    st4(r0 + id,  make_float4(l0.x - b0.x, l0.y - b0.y, l0.z - b0.z, l0.w - b0.w));
    st4(r0 + id1, make_float4(l1.x - b1.x, l1.y - b1.y, l1.z - b1.z, l1.w - b1.w));
}

// two-level restrict: R0(128^3) -> R1(64^3) -> R2(32^3)
__global__ void __launch_bounds__(256)
k_restrict2(const float* __restrict__ r0, float* __restrict__ r1,
            float* __restrict__ r2)
{
    __shared__ float s1[8 * 8 * 8];
    int tid = threadIdx.x;
    int bx = blockIdx.x & 7, by = (blockIdx.x >> 3) & 7, bz = blockIdx.x >> 6;

    #pragma unroll
    for (int q = 0; q < 2; ++q) {
        int idx = tid + q * 256;
        int i = idx & 7, j = (idx >> 3) & 7, k = idx >> 6;
        int gi = bx * 8 + i, gj = by * 8 + j, gk = bz * 8 + k;
        const int t = 128;
        const float* a = r0 + ((size_t)(2 * gk) * t + 2 * gj) * t + 2 * gi;
        float2 a0 = *(const float2*)a;
        float2 a1 = *(const float2*)(a + t);
        float2 a2 = *(const float2*)(a + (size_t)t * t);
        float2 a3 = *(const float2*)(a + (size_t)t * t + t);
        float v = 0.125f * (a0.x + a0.y + a1.x + a1.y + a2.x + a2.y + a3.x + a3.y);
        r1[((size_t)gk * 64 + gj) * 64 + gi] = v;
        s1[idx] = v;
    }
    __syncthreads();

    if (tid < 64) {
        int i = tid & 3, j = (tid >> 2) & 3, k = tid >> 4;
        const int t = 8;
        const float* a = s1 + ((2 * k) * t + 2 * j) * t + 2 * i;
        const float* b = a + t * t;
        float v = 0.125f * (a[0] + a[1] + a[t] + a[t + 1]
                          + b[0] + b[1] + b[t] + b[t + 1]);
        int gi = bx * 4 + i, gj = by * 4 + j, gk = bz * 4 + k;
        r2[((size_t)gk * 32 + gj) * 32 + gi] = v;
    }
}

// ---- fused MG core ----

__device__ __forceinline__ void restrict_stage(const float* __restrict__ src,
                                               float* __restrict__ dst,
                                               int s, int tid)
{
    int n = s * s * s;
    int t = 2 * s;
    for (int idx = tid; idx < n; idx += 1024) {
        int i = idx % s;
        int j = (idx / s) % s;
        int k = idx / (s * s);
        const float* r0 = src + ((size_t)(2 * k) * t + 2 * j) * t + 2 * i;
        const float* r1 = r0 + (size_t)t * t;
        dst[idx] = 0.125f * (r0[0] + r0[1] + r0[t] + r0[t + 1]
                           + r1[0] + r1[1] + r1[t] + r1[t + 1]);
    }
}

__device__ __forceinline__ void smooth_stage(const float* __restrict__ win,
                                             const float* __restrict__ r,
                                             float* __restrict__ out,
                                             int s, int tid, bool win_zero)
{
    int n = s * s * s;
    int t = 2 * s;
    for (int idx = tid; idx < n; idx += 1024) {
        int i = idx % s;
        int j = (idx / s) % s;
        int k = idx / (s * s);
        float nsum = 0.0f;
        if (!win_zero) {
            if (i > 0)     nsum += win[idx - 1];
            if (i < s - 1) nsum += win[idx + 1];
            if (j > 0)     nsum += win[idx - s];
            if (j < s - 1) nsum += win[idx + s];
            if (k > 0)     nsum += win[idx - s * s];
            if (k < s - 1) nsum += win[idx + s * s];
        }
        float wnew = (nsum - r[idx]) * (1.0f / 6.0f);
        size_t o = ((size_t)(2 * k) * t + 2 * j) * t + 2 * i;
        size_t o2 = o + (size_t)t * t;
        out[o] = wnew;      out[o + 1] = wnew;
        out[o + t] = wnew;  out[o + t + 1] = wnew;
        out[o2] = wnew;     out[o2 + 1] = wnew;
        out[o2 + t] = wnew; out[o2 + t + 1] = wnew;
    }
}

__global__ void __launch_bounds__(1024, 1)
k_mgcore(const float* __restrict__ R2g, float* __restrict__ W32g,
         float* __restrict__ out_r)
{
    __shared__ float sR3[4096], sR4[512], sR5[64], sR6[8], sR7[1];
    __shared__ float sW2[8], sW4[64], sW8[512], sW16[4096];
    int tid = threadIdx.x;

    restrict_stage(R2g, sR3, 16, tid); __syncthreads();
    restrict_stage(sR3, sR4, 8, tid);  __syncthreads();
    restrict_stage(sR4, sR5, 4, tid);  __syncthreads();
    restrict_stage(sR5, sR6, 2, tid);  __syncthreads();
    restrict_stage(sR6, sR7, 1, tid);  __syncthreads();
    if (tid == 0) out_r[0] = sR7[0];

    smooth_stage(nullptr, sR7, sW2, 1, tid, true);  __syncthreads();
    smooth_stage(sW2, sR6, sW4, 2, tid, false);     __syncthreads();
    smooth_stage(sW4, sR5, sW8, 4, tid, false);     __syncthreads();
    smooth_stage(sW8, sR4, sW16, 8, tid, false);    __syncthreads();
    smooth_stage(sW16, sR3, W32g, 16, tid, false);
}

// smooth+prolong grid kernel (s=32)
__global__ void k_smoothprol(const float* __restrict__ win, const float* __restrict__ r,
                             float* __restrict__ out, int s)
{
    int idx = blockIdx.x * blockDim.x + threadIdx.x;
    int n = s * s * s;
    if (idx >= n) return;
    int i = idx % s;
    int j = (idx / s) % s;
    int k = idx / (s * s);
    float nsum = 0.0f;
    if (i > 0)     nsum += win[idx - 1];
    if (i < s - 1) nsum += win[idx + 1];
    if (j > 0)     nsum += win[idx - s];
    if (j < s - 1) nsum += win[idx + s];
    if (k > 0)     nsum += win[idx - s * s];
    if (k < s - 1) nsum += win[idx + s * s];
    float wnew = (nsum - r[idx]) * (1.0f / 6.0f);
    int t = 2 * s;
    size_t o = ((size_t)(2 * k) * t + 2 * j) * t + 2 * i;
    size_t o2 = o + (size_t)t * t;
    out[o] = wnew;      out[o + 1] = wnew;
    out[o + t] = wnew;  out[o + t + 1] = wnew;
    out[o2] = wnew;     out[o2 + 1] = wnew;
    out[o2 + t] = wnew; out[o2 + t + 1] = wnew;
}

// s=64 smooth+prolong fused with pressure update; wmg store optional
__global__ void __launch_bounds__(256)
k_spp64(const float* __restrict__ win, const float* __restrict__ r,
        const float* __restrict__ pin, const float* __restrict__ r0,
        float* __restrict__ wmg, float* __restrict__ pout, int store_wmg)
{
    const int s = 64;
    int idx = blockIdx.x * blockDim.x + threadIdx.x;
    int i = idx & 63, j = (idx >> 6) & 63, k = idx >> 12;
    float nsum = 0.0f;
    if (i > 0)     nsum += win[idx - 1];
    if (i < s - 1) nsum += win[idx + 1];
    if (j > 0)     nsum += win[idx - s];
    if (j < s - 1) nsum += win[idx + s];
    if (k > 0)     nsum += win[idx - s * s];
    if (k < s - 1) nsum += win[idx + s * s];
    float wnew = (nsum - r[idx]) * (1.0f / 6.0f);
    const int t = 128;
    size_t o = ((size_t)(2 * k) * t + 2 * j) * t + 2 * i;
    float2 wv = make_float2(wnew, wnew);
    #pragma unroll
    for (int dz = 0; dz < 2; ++dz) {
        #pragma unroll
        for (int dy = 0; dy < 2; ++dy) {
            size_t q = o + (size_t)dz * t * t + (size_t)dy * t;
            float2 pv = *(const float2*)(pin + q);
            float2 rv = *(const float2*)(r0 + q);
            if (store_wmg) *(float2*)(wmg + q) = wv;
            *(float2*)(pout + q) = make_float2(pv.x - wnew + rv.x * (1.0f/6.0f),
                                               pv.y - wnew + rv.y * (1.0f/6.0f));
        }
    }
}

__global__ void __launch_bounds__(256)
k_final(const float* __restrict__ u, const float* __restrict__ v,
        const float* __restrict__ w, const float* __restrict__ p,
        const float* __restrict__ F, const float* __restrict__ dtp,
        float* __restrict__ ou, float* __restrict__ ov,
        float* __restrict__ ow)
{
    int i4 = threadIdx.x * 4;
    int j = blockIdx.y * blockDim.y + threadIdx.y;
    int tz = blockIdx.z * blockDim.z + threadIdx.z;
    int k = tz * 2;
    int id = (k * N + j) * N + i4;
    int id1 = id + N2;
    float dt = dtp[0];

    ZPair P = ldz(p, id, i4, j, k, false);
    VSt P0 = vz0(P), P1 = vz1(P);
    float4 px0 = gradx(P0), py0 = grady(P0), pz0 = gradz(P0);
    float4 px1 = gradx(P1), py1 = grady(P1), pz1 = gradz(P1);
    float4 f0 = ld4(F + id),  f1 = ld4(F + id1);
    float4 uc0 = ld4(u + id), uc1 = ld4(u + id1);
    float4 vc0 = ld4(v + id), vc1 = ld4(v + id1);
    float4 wc0 = ld4(w + id), wc1 = ld4(w + id1);

    st4(ou + id,  make_float4((uc0.x - dt*px0.x)*f0.x, (uc0.y - dt*px0.y)*f0.y,
                              (uc0.z - dt*px0.z)*f0.z, (uc0.w - dt*px0.w)*f0.w));
    st4(ou + id1, make_float4((uc1.x - dt*px1.x)*f1.x, (uc1.y - dt*px1.y)*f1.y,
                              (uc1.z - dt*px1.z)*f1.z, (uc1.w - dt*px1.w)*f1.w));
    st4(ov + id,  make_float4((vc0.x - dt*py0.x)*f0.x, (vc0.y - dt*py0.y)*f0.y,
                              (vc0.z - dt*py0.z)*f0.z, (vc0.w - dt*py0.w)*f0.w));
    st4(ov + id1, make_float4((vc1.x - dt*py1.x)*f1.x, (vc1.y - dt*py1.y)*f1.y,
                              (vc1.z - dt*py1.z)*f1.z, (vc1.w - dt*py1.w)*f1.w));
    st4(ow + id,  make_float4((wc0.x - dt*pz0.x)*f0.x, (wc0.y - dt*pz0.y)*f0.y,
                              (wc0.z - dt*pz0.z)*f0.z, (wc0.w - dt*pz0.w)*f0.w));
    st4(ow + id1, make_float4((wc1.x - dt*pz1.x)*f1.x, (wc1.y - dt*pz1.y)*f1.y,
                              (wc1.z - dt*pz1.z)*f1.z, (wc1.w - dt*pz1.w)*f1.w));
}

// ---------------- host ----------------

static inline dim3 g1(int n) { return dim3((unsigned)((n + 255) / 256)); }

extern "C" void kernel_launch(void* const* d_in, const int* in_sizes, int n_in,
                              void* d_out, int out_size)
{
    const float* vu  = (const float*)d_in[0];
    const float* vv  = (const float*)d_in[1];
    const float* vw  = (const float*)d_in[2];
    const float* vp  = (const float*)d_in[3];
    const float* sg  = (const float*)d_in[4];
    const float* dtp = (const float*)d_in[5];

    float* out = (float*)d_out;
    float* out_u   = out;
    float* out_v   = out + (size_t)1 * N3;
    float* out_w   = out + (size_t)2 * N3;
    float* out_p   = out + (size_t)3 * N3;
    float* out_wmg = out + (size_t)4 * N3;
    float* out_r   = out + (size_t)5 * N3;

    float* SC = nullptr;
    cudaGetSymbolAddress((void**)&SC, g_scratch);

    float* U  = SC + O_U;   float* V  = SC + O_V;   float* W  = SC + O_W;
    float* BU = SC + O_BU;  float* BV = SC + O_BV;  float* BW = SC + O_BW;
    float* B  = SC + O_B;   float* R0 = SC + O_R0;  float* F  = SC + O_F;
    float* R1 = SC + O_R1;  float* R2 = SC + O_R2;
    float* W32 = SC + O_W32; float* W64 = SC + O_W64;

    dim3 TBZ(32, 4, 2), TGZ(1, N / 4, N / 4);   // 4 x-elems, 2 z-planes per thread

    // momentum step
    k_solid<<<N3 / 4 / 256, 256>>>((const float4*)vu, (const float4*)vv,
                                   (const float4*)vw, (const float4*)sg, dtp,
                                   (float4*)U, (float4*)V, (float4*)W, (float4*)F);
    k_predictor<<<TGZ, TBZ>>>(U, V, W, vp, F, dtp, BU, BV, BW);
    k_corrector<<<TGZ, TBZ>>>(BU, BV, BW, vp, F, dtp, U, V, W);

    // multigrid F-cycle, 2 iterations
    for (int it = 0; it < 2; ++it) {
        if (it == 0) {
            k_divres<<<TGZ, TBZ>>>(U, V, W, vp, dtp, B, R0);
        } else {
            k_residual<<<TGZ, TBZ>>>(out_p, B, R0);
        }
        const float* pin = (it == 0) ? vp : out_p;

        k_restrict2<<<512, 256>>>(R0, R1, R2);
        k_mgcore<<<1, 1024>>>(R2, W32, out_r);
        k_smoothprol<<<g1(S32), 256>>>(W32, R2, W64, 32);
        k_spp64<<<g1(S64), 256>>>(W64, R1, pin, R0, out_wmg, out_p, it == 1);
    }

    // final projection + drag
    k_final<<<TGZ, TBZ>>>(U, V, W, out_p, F, dtp, out_u, out_v, out_w);
}

// round 8
// speedup vs baseline: 1.0871x; 1.0871x over previous
#include <cuda_runtime.h>

#define N 128
#define N2 (N*N)
#define N3 (N*N*N)

static constexpr int S64 = 64*64*64;
static constexpr int S32 = 32*32*32;

static constexpr size_t O_U   = 0;
static constexpr size_t O_V   = (size_t)1*N3;
static constexpr size_t O_W   = (size_t)2*N3;
static constexpr size_t O_BU  = (size_t)3*N3;
static constexpr size_t O_BV  = (size_t)4*N3;
static constexpr size_t O_BW  = (size_t)5*N3;
static constexpr size_t O_B   = (size_t)6*N3;
static constexpr size_t O_R0  = (size_t)7*N3;
static constexpr size_t O_F   = (size_t)8*N3;
static constexpr size_t O_R1  = (size_t)9*N3;
static constexpr size_t O_R2  = O_R1 + S64;
static constexpr size_t O_W32 = O_R2 + S32;
static constexpr size_t O_W64 = O_W32 + S32;
static constexpr size_t SCRATCH_TOT = O_W64 + S64;

__device__ float g_scratch[SCRATCH_TOT];

// ---------------- vector helpers ----------------

__device__ __forceinline__ float4 ld4(const float* __restrict__ p) {
    return *(const float4*)p;
}
__device__ __forceinline__ void st4(float* __restrict__ p, float4 v) {
    *(float4*)p = v;
}

struct VSt {             // 7-point stencil data for 4 consecutive x cells
    float4 c;
    float  w, e;
    float4 s, n, b, t;
};

// single-z stencil load (used by heavy kernels: predictor/corrector)
__device__ __forceinline__ VSt ldst(const float* __restrict__ A, int id,
                                    int i4, int j, int k, bool bcu) {
    VSt r;
    r.c = ld4(A + id);
    r.w = (i4 > 0)     ? A[id - 1]  : (bcu ? 1.0f : r.c.x);
    r.e = (i4 < N - 4) ? A[id + 4]  : r.c.w;
    r.s = (j > 0)      ? ld4(A + id - N)  : r.c;
    r.n = (j < N - 1)  ? ld4(A + id + N)  : r.c;
    r.b = (k > 0)      ? ld4(A + id - N2) : r.c;
    r.t = (k < N - 1)  ? ld4(A + id + N2) : r.c;
    return r;
}

// z-pair stencil data (used by light kernels: divres/residual/final)
struct ZPair {
    float4 c0, c1;
    float  w0, e0, w1, e1;
    float4 s0, n0, s1, n1;
    float4 bm, tp;
};

__device__ __forceinline__ ZPair ldz(const float* __restrict__ A, int id,
                                     int i4, int j, int k, bool bcu) {
    ZPair z;
    int id1 = id + N2;
    z.c0 = ld4(A + id);
    z.c1 = ld4(A + id1);
    z.w0 = (i4 > 0)     ? A[id - 1]   : (bcu ? 1.0f : z.c0.x);
    z.e0 = (i4 < N - 4) ? A[id + 4]   : z.c0.w;
    z.w1 = (i4 > 0)     ? A[id1 - 1]  : (bcu ? 1.0f : z.c1.x);
    z.e1 = (i4 < N - 4) ? A[id1 + 4]  : z.c1.w;
    z.s0 = (j > 0)      ? ld4(A + id - N)   : z.c0;
    z.n0 = (j < N - 1)  ? ld4(A + id + N)   : z.c0;
    z.s1 = (j > 0)      ? ld4(A + id1 - N)  : z.c1;
    z.n1 = (j < N - 1)  ? ld4(A + id1 + N)  : z.c1;
    z.bm = (k > 0)      ? ld4(A + id - N2)  : z.c0;
    z.tp = (k + 2 < N)  ? ld4(A + id1 + N2) : z.c1;
    return z;
}

__device__ __forceinline__ VSt vz0(const ZPair& z) {
    VSt r; r.c = z.c0; r.w = z.w0; r.e = z.e0;
    r.s = z.s0; r.n = z.n0; r.b = z.bm; r.t = z.c1; return r;
}
__device__ __forceinline__ VSt vz1(const ZPair& z) {
    VSt r; r.c = z.c1; r.w = z.w1; r.e = z.e1;
    r.s = z.s1; r.n = z.n1; r.b = z.c0; r.t = z.tp; return r;
}

__device__ __forceinline__ float4 westv(const VSt& s) {
    return make_float4(s.w, s.c.x, s.c.y, s.c.z);
}
__device__ __forceinline__ float4 eastv(const VSt& s) {
    return make_float4(s.c.y, s.c.z, s.c.w, s.e);
}
__device__ __forceinline__ float4 gradx(const VSt& s) {
    float4 w = westv(s), e = eastv(s);
    return make_float4(0.5f*(e.x-w.x), 0.5f*(e.y-w.y), 0.5f*(e.z-w.z), 0.5f*(e.w-w.w));
}
__device__ __forceinline__ float4 grady(const VSt& s) {
    return make_float4(0.5f*(s.n.x-s.s.x), 0.5f*(s.n.y-s.s.y),
                       0.5f*(s.n.z-s.s.z), 0.5f*(s.n.w-s.s.w));
}
__device__ __forceinline__ float4 gradz(const VSt& s) {
    return make_float4(0.5f*(s.t.x-s.b.x), 0.5f*(s.t.y-s.b.y),
                       0.5f*(s.t.z-s.b.z), 0.5f*(s.t.w-s.b.w));
}
__device__ __forceinline__ float4 lap4(const VSt& s) {
    float4 w = westv(s), e = eastv(s);
    return make_float4(w.x+e.x+s.s.x+s.n.x+s.b.x+s.t.x-6.f*s.c.x,
                       w.y+e.y+s.s.y+s.n.y+s.b.y+s.t.y-6.f*s.c.y,
                       w.z+e.z+s.s.z+s.n.z+s.b.z+s.t.z-6.f*s.c.z,
                       w.w+e.w+s.s.w+s.n.w+s.b.w+s.t.w-6.f*s.c.w);
}

// (base + cdt*(lap(S) - A1*dSx - A2*dSy - A3*dSz) - dt*grad) * f
__device__ __forceinline__ float4 mom_rhs(const VSt& S, float4 base,
                                          float4 A1, float4 A2, float4 A3,
                                          float4 grad, float4 f,
                                          float cdt, float dt)
{
    float4 wv = westv(S), ev = eastv(S);
    float4 out;
    const float* pw = &wv.x;   const float* pe = &ev.x;
    const float* ps = &S.s.x;  const float* pn = &S.n.x;
    const float* pb = &S.b.x;  const float* pt = &S.t.x;
    const float* pc = &S.c.x;  const float* pba = &base.x;
    const float* p1 = &A1.x;   const float* p2 = &A2.x;  const float* p3 = &A3.x;
    const float* pg = &grad.x; const float* pf = &f.x;
    float* po = &out.x;
    #pragma unroll
    for (int m = 0; m < 4; ++m) {
        float lap = pw[m]+pe[m]+ps[m]+pn[m]+pb[m]+pt[m] - 6.f*pc[m];
        float ax = 0.5f*(pe[m]-pw[m]);
        float ay = 0.5f*(pn[m]-ps[m]);
        float az = 0.5f*(pt[m]-pb[m]);
        po[m] = (pba[m] + cdt*(lap - p1[m]*ax - p2[m]*ay - p3[m]*az) - dt*pg[m]) * pf[m];
    }
    return out;
}

// ---------------- kernels ----------------

__global__ void k_solid(const float4* __restrict__ vu, const float4* __restrict__ vv,
                        const float4* __restrict__ vw, const float4* __restrict__ sg,
                        const float* __restrict__ dtp,
                        float4* __restrict__ u, float4* __restrict__ v,
                        float4* __restrict__ w, float4* __restrict__ F)
{
    int id = blockIdx.x * blockDim.x + threadIdx.x;
    float dt = dtp[0];
    float4 s = sg[id];
    float4 f;
    f.x = __fdividef(1.0f, 1.0f + dt * s.x);
    f.y = __fdividef(1.0f, 1.0f + dt * s.y);
    f.z = __fdividef(1.0f, 1.0f + dt * s.z);
    f.w = __fdividef(1.0f, 1.0f + dt * s.w);
    float4 a = vu[id]; a.x *= f.x; a.y *= f.y; a.z *= f.z; a.w *= f.w; u[id] = a;
    float4 b = vv[id]; b.x *= f.x; b.y *= f.y; b.z *= f.z; b.w *= f.w; v[id] = b;
    float4 c = vw[id]; c.x *= f.x; c.y *= f.y; c.z *= f.z; c.w *= f.w; w[id] = c;
    F[id] = f;
}

// HEAVY kernels: 1 z-plane per thread (R4 shape — best measured)
__global__ void __launch_bounds__(256)
k_predictor(const float* __restrict__ u, const float* __restrict__ v,
            const float* __restrict__ w, const float* __restrict__ p,
            const float* __restrict__ F, const float* __restrict__ dtp,
            float* __restrict__ bu, float* __restrict__ bv,
            float* __restrict__ bw)
{
    int i4 = threadIdx.x * 4;
    int j = blockIdx.y * blockDim.y + threadIdx.y;
    int k = blockIdx.z * blockDim.z + threadIdx.z;
    int id = (k * N + j) * N + i4;
    float dt = dtp[0], hdt = 0.5f * dt;

    float4 f  = ld4(F + id);
    float4 uc = ld4(u + id), vc = ld4(v + id), wc = ld4(w + id);

    VSt P = ldst(p, id, i4, j, k, false);
    float4 px = gradx(P), py = grady(P), pz = gradz(P);

    VSt S = ldst(u, id, i4, j, k, true);
    st4(bu + id, mom_rhs(S, uc, uc, vc, wc, px, f, hdt, dt));
    S = ldst(v, id, i4, j, k, false);
    st4(bv + id, mom_rhs(S, vc, uc, vc, wc, py, f, hdt, dt));
    S = ldst(w, id, i4, j, k, false);
    st4(bw + id, mom_rhs(S, wc, uc, vc, wc, pz, f, hdt, dt));
}

__global__ void __launch_bounds__(256)
k_corrector(const float* __restrict__ bu, const float* __restrict__ bv,
            const float* __restrict__ bw, const float* __restrict__ p,
            const float* __restrict__ F, const float* __restrict__ dtp,
            float* __restrict__ u, float* __restrict__ v,
            float* __restrict__ w)
{
    int i4 = threadIdx.x * 4;
    int j = blockIdx.y * blockDim.y + threadIdx.y;
    int k = blockIdx.z * blockDim.z + threadIdx.z;
    int id = (k * N + j) * N + i4;
    float dt = dtp[0];

    float4 f   = ld4(F + id);
    float4 uc  = ld4(u + id),  vc  = ld4(v + id),  wc  = ld4(w + id);
    float4 buc = ld4(bu + id), bvc = ld4(bv + id), bwc = ld4(bw + id);

    VSt P = ldst(p, id, i4, j, k, false);
    float4 px = gradx(P), py = grady(P), pz = gradz(P);

    VSt S = ldst(bu, id, i4, j, k, true);
    float4 un = mom_rhs(S, uc, buc, bvc, bwc, px, f, dt, dt);
    S = ldst(bv, id, i4, j, k, false);
    float4 vn = mom_rhs(S, vc, buc, bvc, bwc, py, f, dt, dt);
    S = ldst(bw, id, i4, j, k, false);
    float4 wn = mom_rhs(S, wc, buc, bvc, bwc, pz, f, dt, dt);

    st4(u + id, un); st4(v + id, vn); st4(w + id, wn);
}

// LIGHT kernels: 2 z-planes per thread (measured small win)
__global__ void __launch_bounds__(256)
k_divres(const float* __restrict__ u, const float* __restrict__ v,
         const float* __restrict__ w, const float* __restrict__ p,
         const float* __restrict__ dtp,
         float* __restrict__ bArr, float* __restrict__ r0)
{
    int i4 = threadIdx.x * 4;
    int j = blockIdx.y * blockDim.y + threadIdx.y;
    int tz = blockIdx.z * blockDim.z + threadIdx.z;
    int k = tz * 2;
    int id = (k * N + j) * N + i4;
    int id1 = id + N2;
    float nh = -0.5f * __fdividef(1.0f, dtp[0]);

    float4 uc0 = ld4(u + id), uc1 = ld4(u + id1);
    float uw0 = (i4 > 0)     ? u[id - 1]  : 1.0f;
    float ue0 = (i4 < N - 4) ? u[id + 4]  : uc0.w;
    float uw1 = (i4 > 0)     ? u[id1 - 1] : 1.0f;
    float ue1 = (i4 < N - 4) ? u[id1 + 4] : uc1.w;

    float4 vc0 = ld4(v + id), vc1 = ld4(v + id1);
    float4 vs0 = (j > 0)     ? ld4(v + id - N)  : vc0;
    float4 vn0 = (j < N - 1) ? ld4(v + id + N)  : vc0;
    float4 vs1 = (j > 0)     ? ld4(v + id1 - N) : vc1;
    float4 vn1 = (j < N - 1) ? ld4(v + id1 + N) : vc1;

    float4 wc0 = ld4(w + id), wc1 = ld4(w + id1);
    float4 wb = (k > 0)     ? ld4(w + id - N2)  : wc0;
    float4 wt = (k + 2 < N) ? ld4(w + id1 + N2) : wc1;

    ZPair P = ldz(p, id, i4, j, k, false);

    {   // z = k
        float4 wv = make_float4(uw0, uc0.x, uc0.y, uc0.z);
        float4 ev = make_float4(uc0.y, uc0.z, uc0.w, ue0);
        float4 b;
        b.x = nh * ((ev.x - wv.x) + (vn0.x - vs0.x) + (wc1.x - wb.x));
        b.y = nh * ((ev.y - wv.y) + (vn0.y - vs0.y) + (wc1.y - wb.y));
        b.z = nh * ((ev.z - wv.z) + (vn0.z - vs0.z) + (wc1.z - wb.z));
        b.w = nh * ((ev.w - wv.w) + (vn0.w - vs0.w) + (wc1.w - wb.w));
        st4(bArr + id, b);
        float4 lp = lap4(vz0(P));
        st4(r0 + id, make_float4(lp.x - b.x, lp.y - b.y, lp.z - b.z, lp.w - b.w));
    }
    {   // z = k+1
        float4 wv = make_float4(uw1, uc1.x, uc1.y, uc1.z);
        float4 ev = make_float4(uc1.y, uc1.z, uc1.w, ue1);
        float4 b;
        b.x = nh * ((ev.x - wv.x) + (vn1.x - vs1.x) + (wt.x - wc0.x));
        b.y = nh * ((ev.y - wv.y) + (vn1.y - vs1.y) + (wt.y - wc0.y));
        b.z = nh * ((ev.z - wv.z) + (vn1.z - vs1.z) + (wt.z - wc0.z));
        b.w = nh * ((ev.w - wv.w) + (vn1.w - vs1.w) + (wt.w - wc0.w));
        st4(bArr + id1, b);
        float4 lp = lap4(vz1(P));
        st4(r0 + id1, make_float4(lp.x - b.x, lp.y - b.y, lp.z - b.z, lp.w - b.w));
    }
}

__global__ void __launch_bounds__(256)
k_residual(const float* __restrict__ p, const float* __restrict__ b,
           float* __restrict__ r0)
{
    int i4 = threadIdx.x * 4;
    int j = blockIdx.y * blockDim.y + threadIdx.y;
    int tz = blockIdx.z * blockDim.z + threadIdx.z;
    int k = tz * 2;
    int id = (k * N + j) * N + i4;
    int id1 = id + N2;

    ZPair P = ldz(p, id, i4, j, k, false);
    float4 b0 = ld4(b + id), b1 = ld4(b + id1);
    float4 l0 = lap4(vz0(P)), l1 = lap4(vz1(P));
    st4(r0 + id,  make_float4(l0.x - b0.x, l0.y - b0.y, l0.z - b0.z, l0.w - b0.w));
    st4(r0 + id1, make_float4(l1.x - b1.x, l1.y - b1.y, l1.z - b1.z, l1.w - b1.w));
}

// two-level restrict: R0(128^3) -> R1(64^3) -> R2(32^3)
__global__ void __launch_bounds__(256)
k_restrict2(const float* __restrict__ r0, float* __restrict__ r1,
            float* __restrict__ r2)
{
    __shared__ float s1[8 * 8 * 8];
    int tid = threadIdx.x;
    int bx = blockIdx.x & 7, by = (blockIdx.x >> 3) & 7, bz = blockIdx.x >> 6;

    #pragma unroll
    for (int q = 0; q < 2; ++q) {
        int idx = tid + q * 256;
        int i = idx & 7, j = (idx >> 3) & 7, k = idx >> 6;
        int gi = bx * 8 + i, gj = by * 8 + j, gk = bz * 8 + k;
        const int t = 128;
        const float* a = r0 + ((size_t)(2 * gk) * t + 2 * gj) * t + 2 * gi;
        float2 a0 = *(const float2*)a;
        float2 a1 = *(const float2*)(a + t);
        float2 a2 = *(const float2*)(a + (size_t)t * t);
        float2 a3 = *(const float2*)(a + (size_t)t * t + t);
        float v = 0.125f * (a0.x + a0.y + a1.x + a1.y + a2.x + a2.y + a3.x + a3.y);
        r1[((size_t)gk * 64 + gj) * 64 + gi] = v;
        s1[idx] = v;
    }
    __syncthreads();

    if (tid < 64) {
        int i = tid & 3, j = (tid >> 2) & 3, k = tid >> 4;
        const int t = 8;
        const float* a = s1 + ((2 * k) * t + 2 * j) * t + 2 * i;
        const float* b = a + t * t;
        float v = 0.125f * (a[0] + a[1] + a[t] + a[t + 1]
                          + b[0] + b[1] + b[t] + b[t + 1]);
        int gi = bx * 4 + i, gj = by * 4 + j, gk = bz * 4 + k;
        r2[((size_t)gk * 32 + gj) * 32 + gi] = v;
    }
}

// ---- fused MG core ----

__device__ __forceinline__ void restrict_stage(const float* __restrict__ src,
                                               float* __restrict__ dst,
                                               int s, int tid)
{
    int n = s * s * s;
    int t = 2 * s;
    for (int idx = tid; idx < n; idx += 1024) {
        int i = idx % s;
        int j = (idx / s) % s;
        int k = idx / (s * s);
        const float* r0 = src + ((size_t)(2 * k) * t + 2 * j) * t + 2 * i;
        const float* r1 = r0 + (size_t)t * t;
        dst[idx] = 0.125f * (r0[0] + r0[1] + r0[t] + r0[t + 1]
                           + r1[0] + r1[1] + r1[t] + r1[t + 1]);
    }
}

__device__ __forceinline__ void smooth_stage(const float* __restrict__ win,
                                             const float* __restrict__ r,
                                             float* __restrict__ out,
                                             int s, int tid, bool win_zero)
{
    int n = s * s * s;
    int t = 2 * s;
    for (int idx = tid; idx < n; idx += 1024) {
        int i = idx % s;
        int j = (idx / s) % s;
        int k = idx / (s * s);
        float nsum = 0.0f;
        if (!win_zero) {
            if (i > 0)     nsum += win[idx - 1];
            if (i < s - 1) nsum += win[idx + 1];
            if (j > 0)     nsum += win[idx - s];
            if (j < s - 1) nsum += win[idx + s];
            if (k > 0)     nsum += win[idx - s * s];
            if (k < s - 1) nsum += win[idx + s * s];
        }
        float wnew = (nsum - r[idx]) * (1.0f / 6.0f);
        size_t o = ((size_t)(2 * k) * t + 2 * j) * t + 2 * i;
        size_t o2 = o + (size_t)t * t;
        out[o] = wnew;      out[o + 1] = wnew;
        out[o + t] = wnew;  out[o + t + 1] = wnew;
        out[o2] = wnew;     out[o2 + 1] = wnew;
        out[o2 + t] = wnew; out[o2 + t + 1] = wnew;
    }
}

__global__ void __launch_bounds__(1024, 1)
k_mgcore(const float* __restrict__ R2g, float* __restrict__ W32g,
         float* __restrict__ out_r)
{
    __shared__ float sR3[4096], sR4[512], sR5[64], sR6[8], sR7[1];
    __shared__ float sW2[8], sW4[64], sW8[512], sW16[4096];
    int tid = threadIdx.x;

    restrict_stage(R2g, sR3, 16, tid); __syncthreads();
    restrict_stage(sR3, sR4, 8, tid);  __syncthreads();
    restrict_stage(sR4, sR5, 4, tid);  __syncthreads();
    restrict_stage(sR5, sR6, 2, tid);  __syncthreads();
    restrict_stage(sR6, sR7, 1, tid);  __syncthreads();
    if (tid == 0) out_r[0] = sR7[0];

    smooth_stage(nullptr, sR7, sW2, 1, tid, true);  __syncthreads();
    smooth_stage(sW2, sR6, sW4, 2, tid, false);     __syncthreads();
    smooth_stage(sW4, sR5, sW8, 4, tid, false);     __syncthreads();
    smooth_stage(sW8, sR4, sW16, 8, tid, false);    __syncthreads();
    smooth_stage(sW16, sR3, W32g, 16, tid, false);
}

// smooth+prolong grid kernel (s=32)
__global__ void k_smoothprol(const float* __restrict__ win, const float* __restrict__ r,
                             float* __restrict__ out, int s)
{
    int idx = blockIdx.x * blockDim.x + threadIdx.x;
    int n = s * s * s;
    if (idx >= n) return;
    int i = idx % s;
    int j = (idx / s) % s;
    int k = idx / (s * s);
    float nsum = 0.0f;
    if (i > 0)     nsum += win[idx - 1];
    if (i < s - 1) nsum += win[idx + 1];
    if (j > 0)     nsum += win[idx - s];
    if (j < s - 1) nsum += win[idx + s];
    if (k > 0)     nsum += win[idx - s * s];
    if (k < s - 1) nsum += win[idx + s * s];
    float wnew = (nsum - r[idx]) * (1.0f / 6.0f);
    int t = 2 * s;
    size_t o = ((size_t)(2 * k) * t + 2 * j) * t + 2 * i;
    size_t o2 = o + (size_t)t * t;
    out[o] = wnew;      out[o + 1] = wnew;
    out[o + t] = wnew;  out[o + t + 1] = wnew;
    out[o2] = wnew;     out[o2 + 1] = wnew;
    out[o2 + t] = wnew; out[o2 + t + 1] = wnew;
}

// s=64 smooth+prolong fused with pressure update; wmg store optional
__global__ void __launch_bounds__(256)
k_spp64(const float* __restrict__ win, const float* __restrict__ r,
        const float* __restrict__ pin, const float* __restrict__ r0,
        float* __restrict__ wmg, float* __restrict__ pout, int store_wmg)
{
    const int s = 64;
    int idx = blockIdx.x * blockDim.x + threadIdx.x;
    int i = idx & 63, j = (idx >> 6) & 63, k = idx >> 12;
    float nsum = 0.0f;
    if (i > 0)     nsum += win[idx - 1];
    if (i < s - 1) nsum += win[idx + 1];
    if (j > 0)     nsum += win[idx - s];
    if (j < s - 1) nsum += win[idx + s];
    if (k > 0)     nsum += win[idx - s * s];
    if (k < s - 1) nsum += win[idx + s * s];
    float wnew = (nsum - r[idx]) * (1.0f / 6.0f);
    const int t = 128;
    size_t o = ((size_t)(2 * k) * t + 2 * j) * t + 2 * i;
    float2 wv = make_float2(wnew, wnew);
    #pragma unroll
    for (int dz = 0; dz < 2; ++dz) {
        #pragma unroll
        for (int dy = 0; dy < 2; ++dy) {
            size_t q = o + (size_t)dz * t * t + (size_t)dy * t;
            float2 pv = *(const float2*)(pin + q);
            float2 rv = *(const float2*)(r0 + q);
            if (store_wmg) *(float2*)(wmg + q) = wv;
            *(float2*)(pout + q) = make_float2(pv.x - wnew + rv.x * (1.0f/6.0f),
                                               pv.y - wnew + rv.y * (1.0f/6.0f));
        }
    }
}

__global__ void __launch_bounds__(256)
k_final(const float* __restrict__ u, const float* __restrict__ v,
        const float* __restrict__ w, const float* __restrict__ p,
        const float* __restrict__ F, const float* __restrict__ dtp,
        float* __restrict__ ou, float* __restrict__ ov,
        float* __restrict__ ow)
{
    int i4 = threadIdx.x * 4;
    int j = blockIdx.y * blockDim.y + threadIdx.y;
    int tz = blockIdx.z * blockDim.z + threadIdx.z;
    int k = tz * 2;
    int id = (k * N + j) * N + i4;
    int id1 = id + N2;
    float dt = dtp[0];

    ZPair P = ldz(p, id, i4, j, k, false);
    VSt P0 = vz0(P), P1 = vz1(P);
    float4 px0 = gradx(P0), py0 = grady(P0), pz0 = gradz(P0);
    float4 px1 = gradx(P1), py1 = grady(P1), pz1 = gradz(P1);
    float4 f0 = ld4(F + id),  f1 = ld4(F + id1);
    float4 uc0 = ld4(u + id), uc1 = ld4(u + id1);
    float4 vc0 = ld4(v + id), vc1 = ld4(v + id1);
    float4 wc0 = ld4(w + id), wc1 = ld4(w + id1);

    st4(ou + id,  make_float4((uc0.x - dt*px0.x)*f0.x, (uc0.y - dt*px0.y)*f0.y,
                              (uc0.z - dt*px0.z)*f0.z, (uc0.w - dt*px0.w)*f0.w));
    st4(ou + id1, make_float4((uc1.x - dt*px1.x)*f1.x, (uc1.y - dt*px1.y)*f1.y,
                              (uc1.z - dt*px1.z)*f1.z, (uc1.w - dt*px1.w)*f1.w));
    st4(ov + id,  make_float4((vc0.x - dt*py0.x)*f0.x, (vc0.y - dt*py0.y)*f0.y,
                              (vc0.z - dt*py0.z)*f0.z, (vc0.w - dt*py0.w)*f0.w));
    st4(ov + id1, make_float4((vc1.x - dt*py1.x)*f1.x, (vc1.y - dt*py1.y)*f1.y,
                              (vc1.z - dt*py1.z)*f1.z, (vc1.w - dt*py1.w)*f1.w));
    st4(ow + id,  make_float4((wc0.x - dt*pz0.x)*f0.x, (wc0.y - dt*pz0.y)*f0.y,
                              (wc0.z - dt*pz0.z)*f0.z, (wc0.w - dt*pz0.w)*f0.w));
    st4(ow + id1, make_float4((wc1.x - dt*pz1.x)*f1.x, (wc1.y - dt*pz1.y)*f1.y,
                              (wc1.z - dt*pz1.z)*f1.z, (wc1.w - dt*pz1.w)*f1.w));
}

// ---------------- host ----------------

static inline dim3 g1(int n) { return dim3((unsigned)((n + 255) / 256)); }

extern "C" void kernel_launch(void* const* d_in, const int* in_sizes, int n_in,
                              void* d_out, int out_size)
{
    const float* vu  = (const float*)d_in[0];
    const float* vv  = (const float*)d_in[1];
    const float* vw  = (const float*)d_in[2];
    const float* vp  = (const float*)d_in[3];
    const float* sg  = (const float*)d_in[4];
    const float* dtp = (const float*)d_in[5];

    float* out = (float*)d_out;
    float* out_u   = out;
    float* out_v   = out + (size_t)1 * N3;
    float* out_w   = out + (size_t)2 * N3;
    float* out_p   = out + (size_t)3 * N3;
    float* out_wmg = out + (size_t)4 * N3;
    float* out_r   = out + (size_t)5 * N3;

    float* SC = nullptr;
    cudaGetSymbolAddress((void**)&SC, g_scratch);

    float* U  = SC + O_U;   float* V  = SC + O_V;   float* W  = SC + O_W;
    float* BU = SC + O_BU;  float* BV = SC + O_BV;  float* BW = SC + O_BW;
    float* B  = SC + O_B;   float* R0 = SC + O_R0;  float* F  = SC + O_F;
    float* R1 = SC + O_R1;  float* R2 = SC + O_R2;
    float* W32 = SC + O_W32; float* W64 = SC + O_W64;

    dim3 TBV(32, 4, 2), TGV(1, N / 4, N / 2);   // heavy: 4 x-elems, 1 z-plane
    dim3 TBZ(32, 4, 2), TGZ(1, N / 4, N / 4);   // light: 4 x-elems, 2 z-planes

    // momentum step
    k_solid<<<N3 / 4 / 256, 256>>>((const float4*)vu, (const float4*)vv,
                                   (const float4*)vw, (const float4*)sg, dtp,
                                   (float4*)U, (float4*)V, (float4*)W, (float4*)F);
    k_predictor<<<TGV, TBV>>>(U, V, W, vp, F, dtp, BU, BV, BW);
    k_corrector<<<TGV, TBV>>>(BU, BV, BW, vp, F, dtp, U, V, W);

    // multigrid F-cycle, 2 iterations
    for (int it = 0; it < 2; ++it) {
        if (it == 0) {
            k_divres<<<TGZ, TBZ>>>(U, V, W, vp, dtp, B, R0);
        } else {
            k_residual<<<TGZ, TBZ>>>(out_p, B, R0);
        }
        const float* pin = (it == 0) ? vp : out_p;

        k_restrict2<<<512, 256>>>(R0, R1, R2);
        k_mgcore<<<1, 1024>>>(R2, W32, out_r);
        k_smoothprol<<<g1(S32), 256>>>(W32, R2, W64, 32);
        k_spp64<<<g1(S64), 256>>>(W64, R1, pin, R0, out_wmg, out_p, it == 1);
    }

    // final projection + drag
    k_final<<<TGZ, TBZ>>>(U, V, W, out_p, F, dtp, out_u, out_v, out_w);
}